// round 15
// baseline (speedup 1.0000x reference)
#include <cuda_runtime.h>
#include <stdint.h>

// Problem constants (fixed by the reference: V=8192, B=8, T=1024, C=V)
#define BB 8
#define TT 1024
#define CC 8192
#define NCHUNK 128            // 64 columns per warp-chunk -> 128 chunks cover C
#define THALF (TT / 2)        // 512
#define WPB 2                 // warps per block: warp0 = half0, warp1 = half1
#define MAIN_THREADS (WPB * 32)
#define MAIN_GRID (BB * NCHUNK)   // 1024 blocks -> 2048 warps, one wave
#define PF 16                 // pipeline batch; two in flight (regs ~128)

// Scratch (static __device__ — no allocations allowed)
__device__ float g_partial[(size_t)BB * TT * NCHUNK]; // [(b*T+t)*NCHUNK + chunk] : 4 MB
__device__ float g_val[BB * TT];                      // z_y per (b,t), log2 domain
__device__ float g_nll[BB * TT];
__device__ unsigned int g_ticket;

// ---- packed f32x2 helpers (FFMA2/FADD2 — ptxas won't emit these from C++) ----
typedef unsigned long long u64;
__device__ __forceinline__ u64 pkxy(float x, float y) {
    u64 r; asm("mov.b64 %0, {%1, %2};" : "=l"(r) : "f"(x), "f"(y)); return r;
}
__device__ __forceinline__ u64 pk2(float v) { return pkxy(v, v); }
__device__ __forceinline__ u64 add2(u64 a, u64 b) {
    u64 r; asm("add.rn.f32x2 %0, %1, %2;" : "=l"(r) : "l"(a), "l"(b)); return r;
}
__device__ __forceinline__ u64 mul2(u64 a, u64 b) {
    u64 r; asm("mul.rn.f32x2 %0, %1, %2;" : "=l"(r) : "l"(a), "l"(b)); return r;
}
__device__ __forceinline__ u64 fma2(u64 a, u64 b, u64 c) {
    u64 r; asm("fma.rn.f32x2 %0, %1, %2, %3;" : "=l"(r) : "l"(a), "l"(b), "l"(c)); return r;
}
__device__ __forceinline__ void unpk_i(u64 v, unsigned int& lo, unsigned int& hi) {
    asm("mov.b64 {%0, %1}, %2;" : "=r"(lo), "=r"(hi) : "l"(v));
}
__device__ __forceinline__ void unpk_f(u64 v, float& lo, float& hi) {
    asm("mov.b64 {%0, %1}, %2;" : "=f"(lo), "=f"(hi) : "l"(v));
}

// Fused: gather-write logits, causal running mean, per-chunk sum(exp(.)),
// and extraction of the target-column activation (log2 domain).
// One BLOCK = (b, chunk of 64 columns); warp0 handles t in [0,512),
// warp1 handles t in [512,1024) after a sum-only prefix over [0,512).
// Both warps read the SAME 64 columns of the SAME gathered rows for
// t<512 (warp1's prefix == warp0's main reads) — co-scheduling them on
// one SM turns the prefix traffic into local cache hits (__ldca keeps
// the lines in the 228KB L1; each line is read exactly twice).
__global__ void __launch_bounds__(MAIN_THREADS, 8)
pool_kernel(const int* __restrict__ xw, const int* __restrict__ yw,
            const float* __restrict__ emb, float* __restrict__ out)
{
    __shared__ int  xs[TT];
    __shared__ int  ys[TT];
    __shared__ u64  invp[TT];       // packed {log2e/(t+1), log2e/(t+1)}
    __shared__ int  s_is64;

    // Detect index dtype on-device: int64 buffers have 0 in every odd 32-bit
    // word (values < 8192); int32 token data can't have 64 zeros in a row.
    if (threadIdx.x == 0) {
        int all0 = 1;
        #pragma unroll 8
        for (int i = 1; i < 128; i += 2) all0 &= (xw[i] == 0);
        s_is64 = all0;
    }
    __syncthreads();
    const int is64 = s_is64;

    const int b     = blockIdx.x >> 7;         // / NCHUNK
    const int chunk = blockIdx.x & (NCHUNK - 1);
    const int half  = threadIdx.x >> 5;        // warp0 = half0, warp1 = half1
    const int lane  = threadIdx.x & 31;

    for (int i = threadIdx.x; i < TT; i += MAIN_THREADS) {
        const int src = b * TT + i;
        xs[i]   = is64 ? xw[2 * src] : xw[src];
        ys[i]   = is64 ? yw[2 * src] : yw[src];
        invp[i] = pk2(1.4426950408889634f / (float)(i + 1));
    }
    __syncthreads();

    const int col = chunk * 64 + lane * 2;
    const float2* __restrict__ ecol = (const float2*)emb + (col >> 1);
    float2* __restrict__ ocol = (float2*)(out + (size_t)b * TT * CC) + (col >> 1);
    float* __restrict__ pbase = g_partial + (size_t)b * TT * NCHUNK + chunk;
    float* __restrict__ vbase = g_val + b * TT;

    // hoisted packed constants for the exp polynomial
    const u64 kMAG  = pk2(12582912.0f);
    const u64 kNMAG = pk2(-12582912.0f);
    const u64 kNEG1 = pk2(-1.0f);
    const u64 kC4   = pk2(9.6181291e-3f);
    const u64 kC3   = pk2(5.5504109e-2f);
    const u64 kC2   = pk2(2.4022651e-1f);
    const u64 kC1   = pk2(6.9314718e-1f);
    const u64 kONE  = pk2(1.0f);

    u64 s2 = 0;   // packed running column sums

    float2 v0[PF], v1[PF];

    auto ldbatch = [&](float2* v, int t0) {    // t0 = global t; cache in L1
        #pragma unroll
        for (int j = 0; j < PF; j++)
            v[j] = __ldca(ecol + (size_t)xs[t0 + j] * (CC / 2));
    };

    // ---- half 1: sum-only prefix over t in [0, THALF) (pipelined) ----
    if (half) {
        ldbatch(v0, 0);
        for (int t0 = 0; t0 < THALF; t0 += 2 * PF) {
            ldbatch(v1, t0 + PF);
            #pragma unroll
            for (int j = 0; j < PF; j++)
                s2 = add2(s2, pkxy(v0[j].x, v0[j].y));
            if (t0 + 2 * PF < THALF) ldbatch(v0, t0 + 2 * PF);
            #pragma unroll
            for (int j = 0; j < PF; j++)
                s2 = add2(s2, pkxy(v1[j].x, v1[j].y));
        }
    }

    // process one batch of PF timesteps (t0 = global t) already in v[]
    auto process = [&](const float2* v, int t0) {
        float es[PF];
        #pragma unroll
        for (int j = 0; j < PF; j++) {
            const int t = t0 + j;
            s2 = add2(s2, pkxy(v[j].x, v[j].y));
            __stcs(&ocol[(size_t)t * (CC / 2)], v[j]);  // logits: write-once stream
            // z = (s/(t+1))*log2e ; exp(a) = 2^z. No max-subtraction:
            // |a| <= ~6 for N(0,1) emb, fp32-safe.
            const u64 z = mul2(s2, invp[t]);
            const u64 r = add2(z, kMAG);
            const u64 q = add2(r, kNMAG);               // round(z)
            const u64 f = fma2(q, kNEG1, z);            // frac in [-0.5,0.5]
            u64 p = fma2(kC4, f, kC3);
            p = fma2(p, f, kC2);
            p = fma2(p, f, kC1);
            p = fma2(p, f, kONE);                       // ~2^frac
            unsigned int r0, r1, p0, p1;
            unpk_i(r, r0, r1);
            unpk_i(p, p0, p1);
            const float e0 = __int_as_float((int)p0 + ((int)r0 << 23));
            const float e1 = __int_as_float((int)p1 + ((int)r1 << 23));
            es[j] = e0 + e1;
            const int yv = ys[t];
            if ((yv & ~1) == col) {                     // exactly one thread grid-wide
                float z0, z1; unpk_f(z, z0, z1);
                vbase[t] = (yv & 1) ? z1 : z0;          // log2-domain target value
            }
        }
        // PF independent warp sum-trees -> SHFL latency interleaved
        #pragma unroll
        for (int j = 0; j < PF; j++) {
            float e = es[j];
            #pragma unroll
            for (int o = 16; o; o >>= 1)
                e += __shfl_xor_sync(0xffffffffu, e, o);
            es[j] = e;
        }
        if (lane == 0) {
            #pragma unroll
            for (int j = 0; j < PF; j++)
                pbase[(size_t)(t0 + j) * NCHUNK] = es[j];
        }
    };

    // ---- main half: t in [tb, tb+THALF), double-buffered ----
    const int tb = half * THALF;
    ldbatch(v0, tb);
    for (int t0 = 0; t0 < THALF; t0 += 2 * PF) {
        ldbatch(v1, tb + t0 + PF);
        process(v0, tb + t0);
        if (t0 + 2 * PF < THALF) ldbatch(v0, tb + t0 + 2 * PF);
        process(v1, tb + t0 + PF);
    }
}

// Fused finalize: one warp per (b,t) combines 128 chunk partials -> nll;
// the last block to finish reduces all 8192 nll terms -> loss (fixed order,
// deterministic).
__global__ void __launch_bounds__(256)
fin_kernel(float* __restrict__ out, int loss_idx, int nblocks)
{
    const int gw   = blockIdx.x * 8 + (threadIdx.x >> 5);   // (b*T+t), 0..8191
    const int lane = threadIdx.x & 31;
    const float4* __restrict__ p =
        (const float4*)(g_partial + (size_t)gw * NCHUNK);
    const float4 v = p[lane];                  // 128 floats per warp in one LDG.128
    float s = (v.x + v.y) + (v.z + v.w);
    #pragma unroll
    for (int o = 16; o; o >>= 1)
        s += __shfl_xor_sync(0xffffffffu, s, o);
    if (lane == 0) {
        // nll = ln(sum_exp) - a_y ; g_val holds z_y = a_y*log2e
        g_nll[gw] = logf(s) - g_val[gw] * 0.6931471805599453f;
    }

    __shared__ unsigned int s_rank;
    __shared__ float sm[256];
    __threadfence();
    __syncthreads();
    if (threadIdx.x == 0) s_rank = atomicAdd(&g_ticket, 1u);
    __syncthreads();
    if (s_rank == (unsigned int)(nblocks - 1)) {
        float a = 0.0f;
        for (int i = threadIdx.x; i < BB * TT; i += 256)
            a += ((volatile float*)g_nll)[i];
        sm[threadIdx.x] = a;
        __syncthreads();
        #pragma unroll
        for (int o = 128; o; o >>= 1) {
            if (threadIdx.x < o) sm[threadIdx.x] += sm[threadIdx.x + o];
            __syncthreads();
        }
        if (threadIdx.x == 0) {
            out[loss_idx] = sm[0] * (1.0f / (BB * TT));
            g_ticket = 0;                   // reset for next graph replay
        }
    }
}

extern "C" void kernel_launch(void* const* d_in, const int* in_sizes, int n_in,
                              void* d_out, int out_size)
{
    const int*   x   = (const int*)d_in[0];   // token ids (int32 or int64 words)
    const int*   y   = (const int*)d_in[1];
    const float* emb = (const float*)d_in[2];
    float*       out = (float*)d_out;

    const int fin_blocks = (BB * TT) / 8;     // 1024
    pool_kernel<<<MAIN_GRID, MAIN_THREADS>>>(x, y, emb, out);
    fin_kernel<<<fin_blocks, 256>>>(out, out_size - 1, fin_blocks);
}

// round 16
// speedup vs baseline: 1.0577x; 1.0577x over previous
#include <cuda_runtime.h>
#include <stdint.h>

// Problem constants (fixed by the reference: V=8192, B=8, T=1024, C=V)
#define BB 8
#define TT 1024
#define CC 8192
#define NCHUNK 128            // 64 columns per warp-chunk -> 128 chunks cover C
#define NSPLIT 2              // time-axis split
#define THALF (TT / NSPLIT)   // 512
#define WPB 2                 // warps per block
#define MAIN_THREADS (WPB * 32)
#define MAIN_GRID (BB * NCHUNK * NSPLIT / WPB)   // 1024 blocks -> 2048 warps
#define PF 16                 // pipeline batch; two in flight (regs ~128)

// Scratch (static __device__ — no allocations allowed)
__device__ float g_partial[(size_t)BB * TT * NCHUNK]; // [(b*T+t)*NCHUNK + chunk] : 4 MB
__device__ float g_val[BB * TT];                      // z_y per (b,t), log2 domain
__device__ float g_nll[BB * TT];
__device__ unsigned int g_ticket;

// ---- packed f32x2 helpers (FFMA2/FADD2 — ptxas won't emit these from C++) ----
typedef unsigned long long u64;
__device__ __forceinline__ u64 pkxy(float x, float y) {
    u64 r; asm("mov.b64 %0, {%1, %2};" : "=l"(r) : "f"(x), "f"(y)); return r;
}
__device__ __forceinline__ u64 pk2(float v) { return pkxy(v, v); }
__device__ __forceinline__ u64 add2(u64 a, u64 b) {
    u64 r; asm("add.rn.f32x2 %0, %1, %2;" : "=l"(r) : "l"(a), "l"(b)); return r;
}
__device__ __forceinline__ u64 mul2(u64 a, u64 b) {
    u64 r; asm("mul.rn.f32x2 %0, %1, %2;" : "=l"(r) : "l"(a), "l"(b)); return r;
}
__device__ __forceinline__ u64 fma2(u64 a, u64 b, u64 c) {
    u64 r; asm("fma.rn.f32x2 %0, %1, %2, %3;" : "=l"(r) : "l"(a), "l"(b), "l"(c)); return r;
}
__device__ __forceinline__ void unpk_i(u64 v, unsigned int& lo, unsigned int& hi) {
    asm("mov.b64 {%0, %1}, %2;" : "=r"(lo), "=r"(hi) : "l"(v));
}
__device__ __forceinline__ void unpk_f(u64 v, float& lo, float& hi) {
    asm("mov.b64 {%0, %1}, %2;" : "=f"(lo), "=f"(hi) : "l"(v));
}

// Fused: gather-write logits, causal running mean, per-chunk sum(exp(.)),
// and extraction of the target-column activation (log2 domain).
// One warp = (b, chunk of 64 columns, time-half); thread owns 2 adjacent cols.
// half 1 first accumulates a sum-only prefix over t in [0, 512).
__global__ void __launch_bounds__(MAIN_THREADS, 8)
pool_kernel(const int* __restrict__ xw, const int* __restrict__ yw,
            const float* __restrict__ emb, float* __restrict__ out)
{
    __shared__ int  xs[TT];
    __shared__ int  ys[TT];
    __shared__ u64  invp[TT];       // packed {log2e/(t+1), log2e/(t+1)}
    __shared__ int  s_is64;

    // Detect index dtype on-device: int64 buffers have 0 in every odd 32-bit
    // word (values < 8192); int32 token data can't have 64 zeros in a row.
    if (threadIdx.x == 0) {
        int all0 = 1;
        #pragma unroll 8
        for (int i = 1; i < 128; i += 2) all0 &= (xw[i] == 0);
        s_is64 = all0;
    }
    __syncthreads();
    const int is64 = s_is64;

    const int gw    = blockIdx.x * WPB + (threadIdx.x >> 5);
    const int b     = gw >> 8;                 // / (NCHUNK*NSPLIT)
    const int rest  = gw & 255;
    const int half  = rest >> 7;
    const int chunk = rest & (NCHUNK - 1);
    const int lane  = threadIdx.x & 31;

    for (int i = threadIdx.x; i < TT; i += MAIN_THREADS) {
        const int src = b * TT + i;
        xs[i]   = is64 ? xw[2 * src] : xw[src];
        ys[i]   = is64 ? yw[2 * src] : yw[src];
        invp[i] = pk2(1.4426950408889634f / (float)(i + 1));
    }
    __syncthreads();

    const int col = chunk * 64 + lane * 2;
    const float2* __restrict__ ecol = (const float2*)emb + (col >> 1);
    float2* __restrict__ ocol = (float2*)(out + (size_t)b * TT * CC) + (col >> 1);
    float* __restrict__ pbase = g_partial + (size_t)b * TT * NCHUNK + chunk;
    float* __restrict__ vbase = g_val + b * TT;

    // hoisted packed constants for the exp polynomial
    const u64 kMAG  = pk2(12582912.0f);
    const u64 kNMAG = pk2(-12582912.0f);
    const u64 kNEG1 = pk2(-1.0f);
    const u64 kC4   = pk2(9.6181291e-3f);
    const u64 kC3   = pk2(5.5504109e-2f);
    const u64 kC2   = pk2(2.4022651e-1f);
    const u64 kC1   = pk2(6.9314718e-1f);
    const u64 kONE  = pk2(1.0f);

    u64 s2 = 0;   // packed running column sums

    float2 v0[PF], v1[PF];

    auto ldbatch = [&](float2* v, int t0) {    // t0 = global t
        #pragma unroll
        for (int j = 0; j < PF; j++)
            v[j] = __ldcg(ecol + (size_t)xs[t0 + j] * (CC / 2));
    };

    // ---- half 1: sum-only prefix over t in [0, THALF) (pipelined) ----
    if (half) {
        ldbatch(v0, 0);
        for (int t0 = 0; t0 < THALF; t0 += 2 * PF) {
            ldbatch(v1, t0 + PF);
            #pragma unroll
            for (int j = 0; j < PF; j++)
                s2 = add2(s2, pkxy(v0[j].x, v0[j].y));
            if (t0 + 2 * PF < THALF) ldbatch(v0, t0 + 2 * PF);
            #pragma unroll
            for (int j = 0; j < PF; j++)
                s2 = add2(s2, pkxy(v1[j].x, v1[j].y));
        }
    }

    // process one batch of PF timesteps (t0 = global t) already in v[]
    auto process = [&](const float2* v, int t0) {
        float es[PF];
        #pragma unroll
        for (int j = 0; j < PF; j++) {
            const int t = t0 + j;
            s2 = add2(s2, pkxy(v[j].x, v[j].y));
            __stcs(&ocol[(size_t)t * (CC / 2)], v[j]);  // logits: write-once stream
            // z = (s/(t+1))*log2e ; exp(a) = 2^z. No max-subtraction:
            // |a| <= ~6 for N(0,1) emb, fp32-safe.
            const u64 z = mul2(s2, invp[t]);
            const u64 r = add2(z, kMAG);
            const u64 q = add2(r, kNMAG);               // round(z)
            const u64 f = fma2(q, kNEG1, z);            // frac in [-0.5,0.5]
            u64 p = fma2(kC4, f, kC3);
            p = fma2(p, f, kC2);
            p = fma2(p, f, kC1);
            p = fma2(p, f, kONE);                       // ~2^frac
            unsigned int r0, r1, p0, p1;
            unpk_i(r, r0, r1);
            unpk_i(p, p0, p1);
            const float e0 = __int_as_float((int)p0 + ((int)r0 << 23));
            const float e1 = __int_as_float((int)p1 + ((int)r1 << 23));
            es[j] = e0 + e1;
            const int yv = ys[t];
            if ((yv & ~1) == col) {                     // exactly one thread grid-wide
                float z0, z1; unpk_f(z, z0, z1);
                vbase[t] = (yv & 1) ? z1 : z0;          // log2-domain target value
            }
        }
        // PF independent warp sum-trees -> SHFL latency interleaved
        #pragma unroll
        for (int j = 0; j < PF; j++) {
            float e = es[j];
            #pragma unroll
            for (int o = 16; o; o >>= 1)
                e += __shfl_xor_sync(0xffffffffu, e, o);
            es[j] = e;
        }
        if (lane == 0) {
            #pragma unroll
            for (int j = 0; j < PF; j++)
                pbase[(size_t)(t0 + j) * NCHUNK] = es[j];
        }
    };

    // ---- main half: t in [tb, tb+THALF), double-buffered ----
    const int tb = half * THALF;
    ldbatch(v0, tb);
    for (int t0 = 0; t0 < THALF; t0 += 2 * PF) {
        ldbatch(v1, tb + t0 + PF);
        process(v0, tb + t0);
        if (t0 + 2 * PF < THALF) ldbatch(v0, tb + t0 + 2 * PF);
        process(v1, tb + t0 + PF);
    }
}

// Fused finalize: one warp per (b,t) combines 128 chunk partials -> nll;
// the last block to finish reduces all 8192 nll terms -> loss (fixed order,
// deterministic).
__global__ void __launch_bounds__(256)
fin_kernel(float* __restrict__ out, int loss_idx, int nblocks)
{
    const int gw   = blockIdx.x * 8 + (threadIdx.x >> 5);   // (b*T+t), 0..8191
    const int lane = threadIdx.x & 31;
    const float4* __restrict__ p =
        (const float4*)(g_partial + (size_t)gw * NCHUNK);
    const float4 v = p[lane];                  // 128 floats per warp in one LDG.128
    float s = (v.x + v.y) + (v.z + v.w);
    #pragma unroll
    for (int o = 16; o; o >>= 1)
        s += __shfl_xor_sync(0xffffffffu, s, o);
    if (lane == 0) {
        // nll = ln(sum_exp) - a_y ; g_val holds z_y = a_y*log2e
        g_nll[gw] = logf(s) - g_val[gw] * 0.6931471805599453f;
    }

    // Last-block loss reduction. Writers order their g_nll store before the
    // ticket RMW via __threadfence(); the reader orders the ticket load
    // before its g_nll loads via __threadfence(). Loads are then plain
    // (pipelined), with 4 independent accumulators to break the serial
    // FADD/load chain that the old volatile loop had.
    __shared__ unsigned int s_rank;
    __shared__ float sm[256];
    __threadfence();
    __syncthreads();
    if (threadIdx.x == 0) s_rank = atomicAdd(&g_ticket, 1u);
    __syncthreads();
    if (s_rank == (unsigned int)(nblocks - 1)) {
        __threadfence();                       // acquire side of the handoff
        float a0 = 0.0f, a1 = 0.0f, a2 = 0.0f, a3 = 0.0f;
        for (int i = threadIdx.x; i < BB * TT; i += 1024) {
            a0 += __ldcg(&g_nll[i]);
            a1 += __ldcg(&g_nll[i + 256]);
            a2 += __ldcg(&g_nll[i + 512]);
            a3 += __ldcg(&g_nll[i + 768]);
        }
        sm[threadIdx.x] = (a0 + a1) + (a2 + a3);
        __syncthreads();
        #pragma unroll
        for (int o = 128; o; o >>= 1) {
            if (threadIdx.x < o) sm[threadIdx.x] += sm[threadIdx.x + o];
            __syncthreads();
        }
        if (threadIdx.x == 0) {
            out[loss_idx] = sm[0] * (1.0f / (BB * TT));
            g_ticket = 0;                   // reset for next graph replay
        }
    }
}

extern "C" void kernel_launch(void* const* d_in, const int* in_sizes, int n_in,
                              void* d_out, int out_size)
{
    const int*   x   = (const int*)d_in[0];   // token ids (int32 or int64 words)
    const int*   y   = (const int*)d_in[1];
    const float* emb = (const float*)d_in[2];
    float*       out = (float*)d_out;

    const int fin_blocks = (BB * TT) / 8;     // 1024
    pool_kernel<<<MAIN_GRID, MAIN_THREADS>>>(x, y, emb, out);
    fin_kernel<<<fin_blocks, 256>>>(out, out_size - 1, fin_blocks);
}

// round 17
// speedup vs baseline: 1.1177x; 1.0568x over previous
#include <cuda_runtime.h>
#include <stdint.h>

// Problem constants (fixed by the reference: V=8192, B=8, T=1024, C=V)
#define BB 8
#define TT 1024
#define CC 8192
#define NCHUNK 128            // 64 columns per warp-chunk -> 128 chunks cover C
#define NSPLIT 2              // time-axis split
#define THALF (TT / NSPLIT)   // 512
#define WPB 2                 // warps per block
#define MAIN_THREADS (WPB * 32)
#define MAIN_GRID (BB * NCHUNK * NSPLIT / WPB)   // 1024 blocks -> 2048 warps
#define PF 16                 // pipeline batch; two in flight (regs ~128)

// Scratch (static __device__ — no allocations allowed)
__device__ float g_partial[(size_t)BB * TT * NCHUNK]; // [(b*T+t)*NCHUNK + chunk] : 4 MB
__device__ float g_val[BB * TT];                      // z_y per (b,t), log2 domain
__device__ float g_nll[BB * TT];
__device__ unsigned int g_ticket;

// ---- packed f32x2 helpers (FFMA2/FADD2 — ptxas won't emit these from C++) ----
typedef unsigned long long u64;
__device__ __forceinline__ u64 pkxy(float x, float y) {
    u64 r; asm("mov.b64 %0, {%1, %2};" : "=l"(r) : "f"(x), "f"(y)); return r;
}
__device__ __forceinline__ u64 pk2(float v) { return pkxy(v, v); }
__device__ __forceinline__ u64 add2(u64 a, u64 b) {
    u64 r; asm("add.rn.f32x2 %0, %1, %2;" : "=l"(r) : "l"(a), "l"(b)); return r;
}
__device__ __forceinline__ u64 mul2(u64 a, u64 b) {
    u64 r; asm("mul.rn.f32x2 %0, %1, %2;" : "=l"(r) : "l"(a), "l"(b)); return r;
}
__device__ __forceinline__ u64 fma2(u64 a, u64 b, u64 c) {
    u64 r; asm("fma.rn.f32x2 %0, %1, %2, %3;" : "=l"(r) : "l"(a), "l"(b), "l"(c)); return r;
}
__device__ __forceinline__ void unpk_i(u64 v, unsigned int& lo, unsigned int& hi) {
    asm("mov.b64 {%0, %1}, %2;" : "=r"(lo), "=r"(hi) : "l"(v));
}
__device__ __forceinline__ void unpk_f(u64 v, float& lo, float& hi) {
    asm("mov.b64 {%0, %1}, %2;" : "=f"(lo), "=f"(hi) : "l"(v));
}

// Fused: gather-write logits, causal running mean, per-chunk sum(exp(.)),
// and extraction of the target-column activation (log2 domain).
// One warp = (b, chunk of 64 columns, time-half); thread owns 2 adjacent cols.
// half 1 first accumulates a sum-only prefix over t in [0, 512).
__global__ void __launch_bounds__(MAIN_THREADS, 8)
pool_kernel(const int* __restrict__ xw, const int* __restrict__ yw,
            const float* __restrict__ emb, float* __restrict__ out)
{
    __shared__ int  xs[TT];
    __shared__ int  ys[TT];
    __shared__ u64  invp[TT];       // packed {log2e/(t+1), log2e/(t+1)}
    __shared__ int  s_is64;

    // Detect index dtype on-device: int64 buffers have 0 in every odd 32-bit
    // word (values < 8192); int32 token data can't have 64 zeros in a row.
    if (threadIdx.x == 0) {
        int all0 = 1;
        #pragma unroll 8
        for (int i = 1; i < 128; i += 2) all0 &= (xw[i] == 0);
        s_is64 = all0;
    }
    __syncthreads();
    const int is64 = s_is64;

    const int gw    = blockIdx.x * WPB + (threadIdx.x >> 5);
    const int b     = gw >> 8;                 // / (NCHUNK*NSPLIT)
    const int rest  = gw & 255;
    const int half  = rest >> 7;
    const int chunk = rest & (NCHUNK - 1);
    const int lane  = threadIdx.x & 31;

    // Range-limited preamble. Blocks are half-homogeneous (WPB=2, pairs never
    // straddle the 128-chunk boundary), but compute the union defensively.
    {
        const int h0 = ((blockIdx.x * WPB) & 255) >> 7;
        const int h1 = ((blockIdx.x * WPB + WPB - 1) & 255) >> 7;
        const int xs_end = (h0 | h1) ? TT : THALF;        // prefix needs xs only
        const int y_lo   = (h0 & h1) ? THALF : 0;         // main-range tables
        const int y_end  = (h0 | h1) ? TT : THALF;
        for (int i = threadIdx.x; i < xs_end; i += MAIN_THREADS) {
            const int src = b * TT + i;
            xs[i] = is64 ? xw[2 * src] : xw[src];
        }
        for (int i = y_lo + threadIdx.x; i < y_end; i += MAIN_THREADS) {
            const int src = b * TT + i;
            ys[i]   = is64 ? yw[2 * src] : yw[src];
            // fast reciprocal (rcp+mul): error ~2^-22 in a pure scale factor,
            // far below the 1e-3 budget
            invp[i] = pk2(__fdividef(1.4426950408889634f, (float)(i + 1)));
        }
    }
    __syncthreads();

    const int col = chunk * 64 + lane * 2;
    const float2* __restrict__ ecol = (const float2*)emb + (col >> 1);
    float2* __restrict__ ocol = (float2*)(out + (size_t)b * TT * CC) + (col >> 1);
    float* __restrict__ pbase = g_partial + (size_t)b * TT * NCHUNK + chunk;
    float* __restrict__ vbase = g_val + b * TT;

    // hoisted packed constants for the exp polynomial
    const u64 kMAG  = pk2(12582912.0f);
    const u64 kNMAG = pk2(-12582912.0f);
    const u64 kNEG1 = pk2(-1.0f);
    const u64 kC4   = pk2(9.6181291e-3f);
    const u64 kC3   = pk2(5.5504109e-2f);
    const u64 kC2   = pk2(2.4022651e-1f);
    const u64 kC1   = pk2(6.9314718e-1f);
    const u64 kONE  = pk2(1.0f);

    u64 s2 = 0;   // packed running column sums

    float2 v0[PF], v1[PF];

    auto ldbatch = [&](float2* v, int t0) {    // t0 = global t
        #pragma unroll
        for (int j = 0; j < PF; j++)
            v[j] = __ldcg(ecol + (size_t)xs[t0 + j] * (CC / 2));
    };

    // ---- half 1: sum-only prefix over t in [0, THALF) (pipelined) ----
    if (half) {
        ldbatch(v0, 0);
        for (int t0 = 0; t0 < THALF; t0 += 2 * PF) {
            ldbatch(v1, t0 + PF);
            #pragma unroll
            for (int j = 0; j < PF; j++)
                s2 = add2(s2, pkxy(v0[j].x, v0[j].y));
            if (t0 + 2 * PF < THALF) ldbatch(v0, t0 + 2 * PF);
            #pragma unroll
            for (int j = 0; j < PF; j++)
                s2 = add2(s2, pkxy(v1[j].x, v1[j].y));
        }
    }

    // process one batch of PF timesteps (t0 = global t) already in v[]
    auto process = [&](const float2* v, int t0) {
        float es[PF];
        #pragma unroll
        for (int j = 0; j < PF; j++) {
            const int t = t0 + j;
            s2 = add2(s2, pkxy(v[j].x, v[j].y));
            __stcs(&ocol[(size_t)t * (CC / 2)], v[j]);  // logits: write-once stream
            // z = (s/(t+1))*log2e ; exp(a) = 2^z. No max-subtraction:
            // |a| <= ~6 for N(0,1) emb, fp32-safe.
            const u64 z = mul2(s2, invp[t]);
            const u64 r = add2(z, kMAG);
            const u64 q = add2(r, kNMAG);               // round(z)
            const u64 f = fma2(q, kNEG1, z);            // frac in [-0.5,0.5]
            u64 p = fma2(kC4, f, kC3);
            p = fma2(p, f, kC2);
            p = fma2(p, f, kC1);
            p = fma2(p, f, kONE);                       // ~2^frac
            unsigned int r0, r1, p0, p1;
            unpk_i(r, r0, r1);
            unpk_i(p, p0, p1);
            const float e0 = __int_as_float((int)p0 + ((int)r0 << 23));
            const float e1 = __int_as_float((int)p1 + ((int)r1 << 23));
            es[j] = e0 + e1;
            const int yv = ys[t];
            if ((yv & ~1) == col) {                     // exactly one thread grid-wide
                float z0, z1; unpk_f(z, z0, z1);
                vbase[t] = (yv & 1) ? z1 : z0;          // log2-domain target value
            }
        }
        // PF independent warp sum-trees -> SHFL latency interleaved
        #pragma unroll
        for (int j = 0; j < PF; j++) {
            float e = es[j];
            #pragma unroll
            for (int o = 16; o; o >>= 1)
                e += __shfl_xor_sync(0xffffffffu, e, o);
            es[j] = e;
        }
        if (lane == 0) {
            #pragma unroll
            for (int j = 0; j < PF; j++)
                pbase[(size_t)(t0 + j) * NCHUNK] = es[j];
        }
    };

    // ---- main half: t in [tb, tb+THALF), double-buffered ----
    const int tb = half * THALF;
    ldbatch(v0, tb);
    for (int t0 = 0; t0 < THALF; t0 += 2 * PF) {
        ldbatch(v1, tb + t0 + PF);
        process(v0, tb + t0);
        if (t0 + 2 * PF < THALF) ldbatch(v0, tb + t0 + 2 * PF);
        process(v1, tb + t0 + PF);
    }
}

// Fused finalize: one warp per (b,t) combines 128 chunk partials -> nll;
// the last block to finish reduces all 8192 nll terms -> loss (fixed order,
// deterministic). (R12-measured-best form.)
__global__ void __launch_bounds__(256)
fin_kernel(float* __restrict__ out, int loss_idx, int nblocks)
{
    const int gw   = blockIdx.x * 8 + (threadIdx.x >> 5);   // (b*T+t), 0..8191
    const int lane = threadIdx.x & 31;
    const float4* __restrict__ p =
        (const float4*)(g_partial + (size_t)gw * NCHUNK);
    const float4 v = p[lane];                  // 128 floats per warp in one LDG.128
    float s = (v.x + v.y) + (v.z + v.w);
    #pragma unroll
    for (int o = 16; o; o >>= 1)
        s += __shfl_xor_sync(0xffffffffu, s, o);
    if (lane == 0) {
        // nll = ln(sum_exp) - a_y ; g_val holds z_y = a_y*log2e
        g_nll[gw] = logf(s) - g_val[gw] * 0.6931471805599453f;
    }

    __shared__ unsigned int s_rank;
    __shared__ float sm[256];
    __threadfence();
    __syncthreads();
    if (threadIdx.x == 0) s_rank = atomicAdd(&g_ticket, 1u);
    __syncthreads();
    if (s_rank == (unsigned int)(nblocks - 1)) {
        float a = 0.0f;
        for (int i = threadIdx.x; i < BB * TT; i += 256)
            a += ((volatile float*)g_nll)[i];
        sm[threadIdx.x] = a;
        __syncthreads();
        #pragma unroll
        for (int o = 128; o; o >>= 1) {
            if (threadIdx.x < o) sm[threadIdx.x] += sm[threadIdx.x + o];
            __syncthreads();
        }
        if (threadIdx.x == 0) {
            out[loss_idx] = sm[0] * (1.0f / (BB * TT));
            g_ticket = 0;                   // reset for next graph replay
        }
    }
}

extern "C" void kernel_launch(void* const* d_in, const int* in_sizes, int n_in,
                              void* d_out, int out_size)
{
    const int*   x   = (const int*)d_in[0];   // token ids (int32 or int64 words)
    const int*   y   = (const int*)d_in[1];
    const float* emb = (const float*)d_in[2];
    float*       out = (float*)d_out;

    const int fin_blocks = (BB * TT) / 8;     // 1024
    pool_kernel<<<MAIN_GRID, MAIN_THREADS>>>(x, y, emb, out);
    fin_kernel<<<fin_blocks, 256>>>(out, out_size - 1, fin_blocks);
}